// round 5
// baseline (speedup 1.0000x reference)
#include <cuda_runtime.h>

#define BB 2048
#define TT 1024
#define H  32
#define NA 4
#define CH 8
#define NCH (TT / CH)

typedef unsigned long long u64;

// packed f32x2 ops (sm_103a)
#define FMA2(d, a, b, c) \
    asm("fma.rn.f32x2 %0, %1, %2, %3;" : "=l"(d) : "l"(a), "l"(b), "l"(c))
#define ADD2(d, a, b) \
    asm("add.rn.f32x2 %0, %1, %2;" : "=l"(d) : "l"(a), "l"(b))

static __device__ __forceinline__ u64 f2u(float x, float y) {
    u64 r;
    asm("mov.b64 %0, {%1, %2};" : "=l"(r) : "f"(x), "f"(y));
    return r;
}
static __device__ __forceinline__ float2 u2f(u64 v) {
    float2 r;
    asm("mov.b64 {%0, %1}, %2;" : "=f"(r.x), "=f"(r.y) : "l"(v));
    return r;
}
static __device__ __forceinline__ float tanh_fast(float z) {
    float r;
    asm("tanh.approx.f32 %0, %1;" : "=f"(r) : "f"(z));
    return r;
}

__global__ __launch_bounds__(32, 14) void vanilla_rnn_kernel(
    const float* __restrict__ act,   // [B, T, 4]
    const float* __restrict__ rew,   // [B, T, 1]
    const float* __restrict__ W_ih,  // [32, 5]
    const float* __restrict__ W_hh,  // [32, 32]
    const float* __restrict__ b_ih,  // [32]
    const float* __restrict__ b_hh,  // [32]
    const float* __restrict__ W_ro,  // [4, 32]
    const float* __restrict__ b_ro,  // [4]
    float* __restrict__ out)         // [B*T*4 logits][B*32 h_T]
{
    const int lane = threadIdx.x;
    const int b    = blockIdx.x;          // one batch row per warp/block

    __shared__ __align__(16) float  hring[CH][36];   // 8-slot ring of h, padded rows
    __shared__ __align__(16) float  wro_s[NA][36];   // W_ro rows, padded
    __shared__ __align__(16) float4 xbuf[2][10];     // cp.async staging: 8 act + 2 rew

    // --- per-lane weights: lane owns h[lane] -> W_hh row `lane` packed over cols
    u64 wh[16];
    const u64* whh_u = (const u64*)W_hh;
    #pragma unroll
    for (int j = 0; j < 16; j++) wh[j] = whh_u[lane * 16 + j];

    float wip[5];
    #pragma unroll
    for (int k = 0; k < 5; k++) wip[k] = W_ih[lane * 5 + k];
    const float bias = b_ih[lane] + b_hh[lane];

    // readout mapping: lane -> (t_local = lane>>2, action = lane&3)
    const int a_act = lane & 3;
    const int tl    = lane >> 2;
    const float bro = b_ro[a_act];

    // W_ro into padded smem (conflict-free reads: 4 rows offset by 4 banks)
    #pragma unroll
    for (int i = lane; i < NA * H; i += 32) wro_s[i >> 5][i & 31] = W_ro[i];
    hring[CH - 1][lane] = 0.0f;            // h_{-1} = 0 (step 0 reads slot 7)

    const float4* actv = (const float4*)act + (size_t)b * TT;
    const float4* rewv = (const float4*)(rew + (size_t)b * TT);
    float* logits = out + (size_t)b * TT * NA;
    float* hT     = out + (size_t)BB * TT * NA + (size_t)b * H;

    // --- prologue: chunk 0 inputs via plain loads, projected to registers
    float xc[CH];
    {
        float4 af[CH];
        #pragma unroll
        for (int i = 0; i < CH; i++) af[i] = __ldg(actv + i);
        const float4 r0 = __ldg(rewv + 0), r1 = __ldg(rewv + 1);
        const float rs[CH] = {r0.x, r0.y, r0.z, r0.w, r1.x, r1.y, r1.z, r1.w};
        #pragma unroll
        for (int i = 0; i < CH; i++)
            xc[i] = fmaf(af[i].x, wip[0], fmaf(af[i].y, wip[1],
                    fmaf(af[i].z, wip[2], fmaf(af[i].w, wip[3],
                    fmaf(rs[i], wip[4], bias)))));
    }
    __syncwarp();   // smem init visible

    float h = 0.0f;

    #pragma unroll 1
    for (int c = 0; c < NCH; c++) {
        // ---- prefetch chunk c+1 into smem staging (no registers held)
        const int cn = (c + 1 < NCH) ? (c + 1) : (NCH - 1);
        if (lane < 10) {
            const float4* src = (lane < 8) ? (actv + cn * CH + lane)
                                           : (rewv + cn * 2 + (lane - 8));
            unsigned sa = (unsigned)__cvta_generic_to_shared(&xbuf[c & 1][lane]);
            asm volatile("cp.async.ca.shared.global [%0], [%1], 16;"
                         :: "r"(sa), "l"(src));
        }
        asm volatile("cp.async.commit_group;" ::: "memory");

        // ---- 8 serial recurrence steps
        #pragma unroll
        for (int i = 0; i < CH; i++) {
            __syncwarp();   // previous STS visible

            const ulonglong2* hp =
                (const ulonglong2*)hring[(i + CH - 1) & (CH - 1)];
            u64 hv[16];
            #pragma unroll
            for (int j = 0; j < 8; j++) {   // pure broadcast LDS.128
                ulonglong2 q = hp[j];
                hv[2 * j]     = q.x;
                hv[2 * j + 1] = q.y;
            }

            u64 s0 = f2u(xc[i], 0.0f), s1 = 0, s2 = 0, s3 = 0;
            #pragma unroll
            for (int j = 0; j < 4; j++) {   // 4 chains x 4 deep
                FMA2(s0, wh[j],      hv[j],      s0);
                FMA2(s1, wh[4 + j],  hv[4 + j],  s1);
                FMA2(s2, wh[8 + j],  hv[8 + j],  s2);
                FMA2(s3, wh[12 + j], hv[12 + j], s3);
            }
            ADD2(s0, s0, s1);
            ADD2(s2, s2, s3);
            ADD2(s0, s0, s2);
            const float2 d = u2f(s0);
            h = tanh_fast(d.x + d.y);
            hring[i][lane] = h;
        }
        __syncwarp();   // slot 7 STS visible before readout

        // ---- readout: 8 steps x 4 actions = 32 dots, 1 per lane
        {
            const ulonglong2* hp = (const ulonglong2*)hring[tl];
            const ulonglong2* wp = (const ulonglong2*)wro_s[a_act];
            u64 a0 = 0, a1 = 0, a2 = 0, a3 = 0;
            #pragma unroll
            for (int j = 0; j < 4; j++) {
                ulonglong2 hq1 = hp[2 * j], hq2 = hp[2 * j + 1];
                ulonglong2 wq1 = wp[2 * j], wq2 = wp[2 * j + 1];
                FMA2(a0, wq1.x, hq1.x, a0);
                FMA2(a1, wq1.y, hq1.y, a1);
                FMA2(a2, wq2.x, hq2.x, a2);
                FMA2(a3, wq2.y, hq2.y, a3);
            }
            ADD2(a0, a0, a1);
            ADD2(a2, a2, a3);
            ADD2(a0, a0, a2);
            const float2 d = u2f(a0);
            // (c*8 + tl)*4 + a_act == c*32 + lane  -> fully coalesced 128B store
            logits[(size_t)c * 32 + lane] = d.x + d.y + bro;
        }

        // ---- project chunk c+1 (cp.async has had 8 steps of slack)
        {
            asm volatile("cp.async.wait_group 0;" ::: "memory");
            __syncwarp();
            const float4* xb = &xbuf[c & 1][0];
            const float4 r0 = xb[8], r1 = xb[9];
            const float rs[CH] = {r0.x, r0.y, r0.z, r0.w,
                                  r1.x, r1.y, r1.z, r1.w};
            #pragma unroll
            for (int i = 0; i < CH; i++) {
                const float4 af = xb[i];
                xc[i] = fmaf(af.x, wip[0], fmaf(af.y, wip[1],
                        fmaf(af.z, wip[2], fmaf(af.w, wip[3],
                        fmaf(rs[i], wip[4], bias)))));
            }
        }
    }

    // final hidden state: lane owns h[lane] (from t = 1023)
    hT[lane] = h;
}

extern "C" void kernel_launch(void* const* d_in, const int* in_sizes, int n_in,
                              void* d_out, int out_size) {
    const float* act  = (const float*)d_in[0];
    const float* rew  = (const float*)d_in[1];
    const float* W_ih = (const float*)d_in[2];
    const float* W_hh = (const float*)d_in[3];
    const float* b_ih = (const float*)d_in[4];
    const float* b_hh = (const float*)d_in[5];
    const float* W_ro = (const float*)d_in[6];
    const float* b_ro = (const float*)d_in[7];
    float* out = (float*)d_out;

    // 1 row per warp, 1 warp per block -> 2048 blocks, ~14 warps/SM resident.
    vanilla_rnn_kernel<<<BB, 32>>>(act, rew, W_ih, W_hh, b_ih, b_hh,
                                   W_ro, b_ro, out);
}